// round 4
// baseline (speedup 1.0000x reference)
#include <cuda_runtime.h>
#include <math_constants.h>

#define NB 256
#define NQ 1000
#define NC 80
#define NN 80000          // NQ * NC per batch
#define TOPK 300
#define NT 1024
#define GSIZE 4096        // fallback group size
#define CAP 6144          // smem candidate buffer entries (u64)
#define CAPG 6144         // global per-batch candidate cap
#define LISTCAP 2048
#define HBINS 2048
#define TSAMP 64          // sample-rank target for streaming threshold
#define TSEL 384          // final selection rank (slack over 300)
#define SCH 4096          // elements per stream CTA

// ---------------- global scratch (static __device__, no allocs) ----------------
__device__ unsigned long long g_buf[NB][CAPG];
__device__ int g_cnt[NB];
__device__ float g_thrf[NB];

// ---------- monotone float<->uint mapping ----------
__device__ __forceinline__ unsigned flipf(unsigned b) {
    return (b & 0x80000000u) ? ~b : (b | 0x80000000u);
}
__device__ __forceinline__ unsigned unflipf(unsigned u) {
    return (u & 0x80000000u) ? (u & 0x7FFFFFFFu) : ~u;
}

// ---------- sigmoid matching XLA: logistic(x) = 0.5 + 0.5*tanh(0.5*x) ----------
__device__ __forceinline__ float sigmoid_ref(float x) {
    float hx = __fmul_rn(0.5f, x);
    float ax = fabsf(hx);
    float xc = fminf(fmaxf(hx, -9.0f), 9.0f);
    float x2 = __fmul_rn(xc, xc);
    float p = -2.76076847742355e-16f;
    p = fmaf(x2, p, 2.00018790482477e-13f);
    p = fmaf(x2, p, -8.60467152213735e-11f);
    p = fmaf(x2, p, 5.12229709037114e-08f);
    p = fmaf(x2, p, 1.48572235717979e-05f);
    p = fmaf(x2, p, 6.37261928875436e-04f);
    p = fmaf(x2, p, 4.89352455891786e-03f);
    p = __fmul_rn(xc, p);
    float q = 1.19825839466702e-06f;
    q = fmaf(x2, q, 1.18534705686654e-04f);
    q = fmaf(x2, q, 2.26843463243900e-03f);
    q = fmaf(x2, q, 4.89352518554385e-03f);
    float t = __fdiv_rn(p, q);
    t = (ax < 4e-4f) ? hx : t;
    return __fadd_rn(__fmul_rn(0.5f, t), 0.5f);
}

// ---------- warp-aggregated appends ----------
__device__ __forceinline__ void append_smem(unsigned long long* buf, int* cnt,
                                            unsigned ub, unsigned idx) {
    unsigned long long key = ((unsigned long long)ub << 32) | idx;
    unsigned mask = __activemask();
    int lane = threadIdx.x & 31;
    int leader = __ffs(mask) - 1;
    int pos = 0;
    if (lane == leader) pos = atomicAdd(cnt, __popc(mask));
    pos = __shfl_sync(mask, pos, leader) + __popc(mask & ((1u << lane) - 1u));
    if (pos < CAP) buf[pos] = key;
}
__device__ __forceinline__ void append_gmem(unsigned long long* gb, int* cnt,
                                            unsigned ub, unsigned idx) {
    unsigned long long key = ((unsigned long long)ub << 32) | idx;
    unsigned mask = __activemask();
    int lane = threadIdx.x & 31;
    int leader = __ffs(mask) - 1;
    int pos = 0;
    if (lane == leader) pos = atomicAdd(cnt, __popc(mask));
    pos = __shfl_sync(mask, pos, leader) + __popc(mask & ((1u << lane) - 1u));
    if (pos < CAPG) gb[pos] = key;
}

// ---------- fast block suffix scan over 2048 bins (shfl-based) ----------
__device__ __forceinline__ void suffix_scan(unsigned* hist, unsigned* wsum) {
    const int tid = threadIdx.x;
    const int lane = tid & 31;
    const int w = tid >> 5;
    unsigned x0 = hist[2047 - 2 * tid];
    unsigned x1 = hist[2046 - 2 * tid];
    unsigned s = x0 + x1;
    unsigned incl = s;
    #pragma unroll
    for (int o = 1; o < 32; o <<= 1) {
        unsigned v = __shfl_up_sync(0xFFFFFFFFu, incl, o);
        if (lane >= o) incl += v;
    }
    if (lane == 31) wsum[w] = incl;
    unsigned excl_lane = incl - s;
    __syncthreads();
    if (tid < 32) {
        unsigned v = wsum[tid];
        unsigned wincl = v;
        #pragma unroll
        for (int o = 1; o < 32; o <<= 1) {
            unsigned t2 = __shfl_up_sync(0xFFFFFFFFu, wincl, o);
            if (tid >= o) wincl += t2;
        }
        wsum[tid] = wincl - v;
    }
    __syncthreads();
    unsigned excl = wsum[w] + excl_lane;
    hist[2047 - 2 * tid] = excl + x0;
    hist[2046 - 2 * tid] = excl + x0 + x1;
    __syncthreads();
}

// ---------- histogram radix-select over smem buffer ----------
__device__ void run_select(unsigned long long* buf, unsigned long long* lst,
                           unsigned* hist, unsigned* wsum, int* sc, int n, int target) {
    const int tid = threadIdx.x;
    if (n <= target) {
        if (tid == 0) { sc[0] = 0; sc[1] = 0; sc[2] = 0; sc[3] = n; }
        __syncthreads();
        for (int i = tid; i < n; i += NT) lst[i] = buf[i];
        __syncthreads();
        return;
    }
    hist[tid] = 0; hist[tid + NT] = 0;
    __syncthreads();
    for (int i = tid; i < n; i += NT)
        atomicAdd(&hist[(unsigned)(buf[i] >> 53)], 1u);
    __syncthreads();
    suffix_scan(hist, wsum);
    {
        unsigned s0 = hist[tid];
        unsigned s0n = (tid + 1 < HBINS) ? hist[tid + 1] : 0u;
        if (s0 >= (unsigned)target && s0n < (unsigned)target) { sc[0] = tid; sc[4] = (int)s0n; }
        unsigned s1 = hist[tid + NT];
        unsigned s1n = (tid + NT + 1 < HBINS) ? hist[tid + NT + 1] : 0u;
        if (s1 >= (unsigned)target && s1n < (unsigned)target) { sc[0] = tid + NT; sc[4] = (int)s1n; }
    }
    if (tid == 0) { sc[2] = 0; sc[3] = 0; }
    __syncthreads();
    const int B = sc[0];
    const int nAbove = sc[4];
    const int selcount = (int)hist[B];
    int refined = 0, B2 = 0;
    if (selcount > 1024) {
        __syncthreads();
        hist[tid] = 0; hist[tid + NT] = 0;
        __syncthreads();
        for (int i = tid; i < n; i += NT) {
            unsigned long long k = buf[i];
            if ((unsigned)(k >> 53) == (unsigned)B)
                atomicAdd(&hist[(unsigned)(k >> 42) & 0x7FFu], 1u);
        }
        __syncthreads();
        suffix_scan(hist, wsum);
        int extra = target - nAbove;
        {
            unsigned s0 = hist[tid];
            unsigned s0n = (tid + 1 < HBINS) ? hist[tid + 1] : 0u;
            if (s0 >= (unsigned)extra && s0n < (unsigned)extra) sc[1] = tid;
            unsigned s1 = hist[tid + NT];
            unsigned s1n = (tid + NT + 1 < HBINS) ? hist[tid + NT + 1] : 0u;
            if (s1 >= (unsigned)extra && s1n < (unsigned)extra) sc[1] = tid + NT;
        }
        if (tid == 0) sc[2] = 1;
        __syncthreads();
        refined = 1;
        B2 = sc[1];
    }
    for (int i = tid; i < n; i += NT) {
        unsigned long long k = buf[i];
        unsigned bin = (unsigned)(k >> 53);
        bool sel = (bin > (unsigned)B) ||
                   (bin == (unsigned)B &&
                    (!refined || (((unsigned)(k >> 42) & 0x7FFu) >= (unsigned)B2)));
        if (sel) {
            int p = atomicAdd(&sc[3], 1);
            if (p < LISTCAP) lst[p] = k;
        }
    }
    __syncthreads();
}

// ================= kernel A: per-batch threshold from 4096-sample =================
extern "C" __global__ void __launch_bounds__(NT)
thresh_kernel(const float* __restrict__ logits) {
    __shared__ unsigned hist[HBINS];
    __shared__ unsigned wsum[32];
    __shared__ int s_bin;
    const int tid = threadIdx.x;
    const int b = blockIdx.x;
    const float* Lp = logits + (size_t)b * NN;

    hist[tid] = 0; hist[tid + NT] = 0;
    if (tid == 0) { s_bin = 0; g_cnt[b] = 0; }
    __syncthreads();
    {
        float4 v = *reinterpret_cast<const float4*>(Lp + tid * 4);
        atomicAdd(&hist[flipf(__float_as_uint(v.x)) >> 21], 1u);
        atomicAdd(&hist[flipf(__float_as_uint(v.y)) >> 21], 1u);
        atomicAdd(&hist[flipf(__float_as_uint(v.z)) >> 21], 1u);
        atomicAdd(&hist[flipf(__float_as_uint(v.w)) >> 21], 1u);
    }
    __syncthreads();
    suffix_scan(hist, wsum);
    {
        unsigned s0 = hist[tid];
        unsigned s0n = (tid + 1 < HBINS) ? hist[tid + 1] : 0u;
        if (s0 >= TSAMP && s0n < TSAMP) s_bin = tid;
        unsigned s1 = hist[tid + NT];
        unsigned s1n = (tid + NT + 1 < HBINS) ? hist[tid + NT + 1] : 0u;
        if (s1 >= TSAMP && s1n < TSAMP) s_bin = tid + NT;
    }
    __syncthreads();
    if (tid == 0) {
        g_thrf[b] = (s_bin == 0) ? -CUDART_INF_F
                                 : __uint_as_float(unflipf((unsigned)s_bin << 21));
    }
}

// ================= kernel B: full-bandwidth filter stream =================
extern "C" __global__ void __launch_bounds__(256)
stream_kernel(const float* __restrict__ logits) {
    const int tid = threadIdx.x;
    const int chunk = blockIdx.x;          // 0..19
    const int b = blockIdx.y;              // 0..255
    const float* Lp = logits + (size_t)b * NN + chunk * SCH;
    const int rem = NN - chunk * SCH;      // last chunk: 2152... (NN - 19*4096 = 2176)
    const float thr = g_thrf[b];
    unsigned long long* gb = g_buf[b];

    float4 v[4];
    bool ok[4];
    #pragma unroll
    for (int i = 0; i < 4; ++i) {          // 4 independent loads up front (MLP)
        int off = i * 1024 + tid * 4;
        ok[i] = off < rem;
        if (ok[i]) v[i] = __ldcs(reinterpret_cast<const float4*>(Lp + off));
    }
    #pragma unroll
    for (int i = 0; i < 4; ++i) {
        if (!ok[i]) continue;
        int base = chunk * SCH + i * 1024 + tid * 4;
        float4 w = v[i];
        if (w.x >= thr) append_gmem(gb, &g_cnt[b], flipf(__float_as_uint(w.x)), base);
        if (w.y >= thr) append_gmem(gb, &g_cnt[b], flipf(__float_as_uint(w.y)), base + 1);
        if (w.z >= thr) append_gmem(gb, &g_cnt[b], flipf(__float_as_uint(w.z)), base + 2);
        if (w.w >= thr) append_gmem(gb, &g_cnt[b], flipf(__float_as_uint(w.w)), base + 3);
    }
}

// ================= kernel C: select + sigmoid + exact rank + write =================
extern "C" __global__ void __launch_bounds__(NT)
select_kernel(const float* __restrict__ logits,
              const float* __restrict__ boxes,
              float* __restrict__ out) {
    extern __shared__ unsigned char smem_raw[];
    unsigned long long* buf = reinterpret_cast<unsigned long long*>(smem_raw);
    unsigned long long* lst = buf + CAP;
    unsigned* hist = reinterpret_cast<unsigned*>(lst + LISTCAP);
    __shared__ unsigned wsum[32];
    __shared__ int s_count;
    __shared__ int sc[5];

    const int tid = threadIdx.x;
    const int b = blockIdx.x;
    const float* Lp = logits + (size_t)b * NN;
    const int gcnt = g_cnt[b];
    int m;

    if (gcnt <= CAPG) {
        m = gcnt;
        for (int i = tid; i < m; i += NT) buf[i] = g_buf[b][i];
        __syncthreads();
    } else {
        // ---------- overflow fallback: adaptive multi-pass (never taken normally) ----------
        if (tid == 0) s_count = 0;
        __syncthreads();
        unsigned thr = 0u;
        for (int g = 0; g < 20; ++g) {
            int base = g * GSIZE + tid * 4;
            if (base < NN) {
                float4 v = *reinterpret_cast<const float4*>(Lp + base);
                unsigned ubs[4] = {flipf(__float_as_uint(v.x)), flipf(__float_as_uint(v.y)),
                                   flipf(__float_as_uint(v.z)), flipf(__float_as_uint(v.w))};
                #pragma unroll
                for (int e = 0; e < 4; ++e)
                    if (ubs[e] >= thr) append_smem(buf, &s_count, ubs[e], base + e);
            }
            __syncthreads();
            if (g == 0 || s_count > CAP - GSIZE) {
                int n = min(s_count, CAP);
                run_select(buf, lst, hist, wsum, sc, n, TSEL);
                int mm = min(sc[3], LISTCAP);
                for (int i = tid; i < mm; i += NT) buf[i] = lst[i];
                __syncthreads();
                if (tid == 0) s_count = mm;
                __syncthreads();
                thr = sc[2] ? (((unsigned)sc[0] << 21) | ((unsigned)sc[1] << 10))
                            : ((unsigned)sc[0] << 21);
            }
        }
        m = min(s_count, CAP);
    }

    // prune to ~TSEL best
    run_select(buf, lst, hist, wsum, sc, m, TSEL);
    int msel = min(sc[3], LISTCAP);

    // sigmoid rank keys: score desc, index asc
    for (int i = tid; i < msel; i += NT) {
        unsigned long long k = lst[i];
        unsigned u = (unsigned)(k >> 32);
        unsigned idx = (unsigned)k;
        float s = sigmoid_ref(__uint_as_float(unflipf(u)));
        lst[i] = ((unsigned long long)__float_as_uint(s) << 32) |
                 (unsigned)(0xFFFFFFFFu - idx);
    }
    __syncthreads();

    for (int i = tid; i < msel; i += NT) {
        unsigned long long k = lst[i];
        int r = 0;
        for (int j = 0; j < msel; ++j) r += (lst[j] > k) ? 1 : 0;
        if (r < TOPK) {
            unsigned idx = 0xFFFFFFFFu - (unsigned)k;
            float s = __uint_as_float((unsigned)(k >> 32));
            int q = (int)(idx / NC);
            int c = (int)(idx - (unsigned)q * NC);
            size_t o = (size_t)b * TOPK + (size_t)r;
            out[o] = (float)c;                                   // labels
            float4 bx = *reinterpret_cast<const float4*>(
                boxes + ((size_t)b * NQ + (size_t)q) * 4);
            float4 xy;
            xy.x = bx.x - 0.5f * bx.z;
            xy.y = bx.y - 0.5f * bx.w;
            xy.z = bx.x + 0.5f * bx.z;
            xy.w = bx.y + 0.5f * bx.w;
            *reinterpret_cast<float4*>(out + (size_t)NB * TOPK + o * 4) = xy;  // boxes
            out[(size_t)NB * TOPK * 5 + o] = s;                  // scores
        }
    }
}

extern "C" void kernel_launch(void* const* d_in, const int* in_sizes, int n_in,
                              void* d_out, int out_size) {
    const float* logits = (const float*)d_in[0];
    const float* boxes = (const float*)d_in[1];
    size_t smem = (size_t)CAP * 8 + (size_t)LISTCAP * 8 + (size_t)HBINS * 4; // 73728 B
    cudaFuncSetAttribute(select_kernel,
                         cudaFuncAttributeMaxDynamicSharedMemorySize, (int)smem);
    thresh_kernel<<<NB, NT>>>(logits);
    dim3 sg(20, NB, 1);
    stream_kernel<<<sg, 256>>>(logits);
    select_kernel<<<NB, NT, smem>>>(logits, boxes, (float*)d_out);
}

// round 5
// speedup vs baseline: 2.9147x; 2.9147x over previous
#include <cuda_runtime.h>
#include <math_constants.h>

#define NB 256
#define NQ 1000
#define NC 80
#define NN 80000          // NQ * NC per batch
#define TOPK 300
#define NT 1024
#define GSIZE 4096        // fallback group size
#define CAP 6144          // smem candidate buffer entries (u64)
#define CAPG 6144         // global per-batch candidate cap
#define LISTCAP 2048
#define HBINS 2048
#define TSAMP 64          // sample-rank target for streaming threshold
#define TSEL 384          // final selection rank (slack over 300)
#define SCH 4096          // elements per stream CTA

// ---------------- global scratch (static __device__, no allocs) ----------------
// g_cnt padded to one 128B line per batch: contiguous counters collide in a few
// LTS slices and serialize ALL grid-wide atomics (round-4 regression mechanism).
__device__ unsigned long long g_buf[NB][CAPG];
__device__ int g_cnt[NB][32];
__device__ float g_thrf[NB];

// ---------- monotone float<->uint mapping ----------
__device__ __forceinline__ unsigned flipf(unsigned b) {
    return (b & 0x80000000u) ? ~b : (b | 0x80000000u);
}
__device__ __forceinline__ unsigned unflipf(unsigned u) {
    return (u & 0x80000000u) ? (u & 0x7FFFFFFFu) : ~u;
}

// ---------- sigmoid matching XLA: logistic(x) = 0.5 + 0.5*tanh(0.5*x) ----------
__device__ __forceinline__ float sigmoid_ref(float x) {
    float hx = __fmul_rn(0.5f, x);
    float ax = fabsf(hx);
    float xc = fminf(fmaxf(hx, -9.0f), 9.0f);
    float x2 = __fmul_rn(xc, xc);
    float p = -2.76076847742355e-16f;
    p = fmaf(x2, p, 2.00018790482477e-13f);
    p = fmaf(x2, p, -8.60467152213735e-11f);
    p = fmaf(x2, p, 5.12229709037114e-08f);
    p = fmaf(x2, p, 1.48572235717979e-05f);
    p = fmaf(x2, p, 6.37261928875436e-04f);
    p = fmaf(x2, p, 4.89352455891786e-03f);
    p = __fmul_rn(xc, p);
    float q = 1.19825839466702e-06f;
    q = fmaf(x2, q, 1.18534705686654e-04f);
    q = fmaf(x2, q, 2.26843463243900e-03f);
    q = fmaf(x2, q, 4.89352518554385e-03f);
    float t = __fdiv_rn(p, q);
    t = (ax < 4e-4f) ? hx : t;
    return __fadd_rn(__fmul_rn(0.5f, t), 0.5f);
}

// ---------- warp-aggregated appends ----------
__device__ __forceinline__ void append_smem(unsigned long long* buf, int* cnt,
                                            unsigned ub, unsigned idx) {
    unsigned long long key = ((unsigned long long)ub << 32) | idx;
    unsigned mask = __activemask();
    int lane = threadIdx.x & 31;
    int leader = __ffs(mask) - 1;
    int pos = 0;
    if (lane == leader) pos = atomicAdd(cnt, __popc(mask));
    pos = __shfl_sync(mask, pos, leader) + __popc(mask & ((1u << lane) - 1u));
    if (pos < CAP) buf[pos] = key;
}
__device__ __forceinline__ void append_gmem(unsigned long long* gb, int* cnt,
                                            unsigned ub, unsigned idx) {
    unsigned long long key = ((unsigned long long)ub << 32) | idx;
    unsigned mask = __activemask();
    int lane = threadIdx.x & 31;
    int leader = __ffs(mask) - 1;
    int pos = 0;
    if (lane == leader) pos = atomicAdd(cnt, __popc(mask));
    pos = __shfl_sync(mask, pos, leader) + __popc(mask & ((1u << lane) - 1u));
    if (pos < CAPG) gb[pos] = key;
}

// ---------- fast block suffix scan over 2048 bins (shfl-based) ----------
__device__ __forceinline__ void suffix_scan(unsigned* hist, unsigned* wsum) {
    const int tid = threadIdx.x;
    const int lane = tid & 31;
    const int w = tid >> 5;
    unsigned x0 = hist[2047 - 2 * tid];
    unsigned x1 = hist[2046 - 2 * tid];
    unsigned s = x0 + x1;
    unsigned incl = s;
    #pragma unroll
    for (int o = 1; o < 32; o <<= 1) {
        unsigned v = __shfl_up_sync(0xFFFFFFFFu, incl, o);
        if (lane >= o) incl += v;
    }
    if (lane == 31) wsum[w] = incl;
    unsigned excl_lane = incl - s;
    __syncthreads();
    if (tid < 32) {
        unsigned v = wsum[tid];
        unsigned wincl = v;
        #pragma unroll
        for (int o = 1; o < 32; o <<= 1) {
            unsigned t2 = __shfl_up_sync(0xFFFFFFFFu, wincl, o);
            if (tid >= o) wincl += t2;
        }
        wsum[tid] = wincl - v;
    }
    __syncthreads();
    unsigned excl = wsum[w] + excl_lane;
    hist[2047 - 2 * tid] = excl + x0;
    hist[2046 - 2 * tid] = excl + x0 + x1;
    __syncthreads();
}

// ---------- histogram radix-select over smem buffer ----------
__device__ void run_select(unsigned long long* buf, unsigned long long* lst,
                           unsigned* hist, unsigned* wsum, int* sc, int n, int target) {
    const int tid = threadIdx.x;
    if (n <= target) {
        if (tid == 0) { sc[0] = 0; sc[1] = 0; sc[2] = 0; sc[3] = n; }
        __syncthreads();
        for (int i = tid; i < n; i += NT) lst[i] = buf[i];
        __syncthreads();
        return;
    }
    hist[tid] = 0; hist[tid + NT] = 0;
    __syncthreads();
    for (int i = tid; i < n; i += NT)
        atomicAdd(&hist[(unsigned)(buf[i] >> 53)], 1u);
    __syncthreads();
    suffix_scan(hist, wsum);
    {
        unsigned s0 = hist[tid];
        unsigned s0n = (tid + 1 < HBINS) ? hist[tid + 1] : 0u;
        if (s0 >= (unsigned)target && s0n < (unsigned)target) { sc[0] = tid; sc[4] = (int)s0n; }
        unsigned s1 = hist[tid + NT];
        unsigned s1n = (tid + NT + 1 < HBINS) ? hist[tid + NT + 1] : 0u;
        if (s1 >= (unsigned)target && s1n < (unsigned)target) { sc[0] = tid + NT; sc[4] = (int)s1n; }
    }
    if (tid == 0) { sc[2] = 0; sc[3] = 0; }
    __syncthreads();
    const int B = sc[0];
    const int nAbove = sc[4];
    const int selcount = (int)hist[B];
    int refined = 0, B2 = 0;
    if (selcount > 1024) {
        __syncthreads();
        hist[tid] = 0; hist[tid + NT] = 0;
        __syncthreads();
        for (int i = tid; i < n; i += NT) {
            unsigned long long k = buf[i];
            if ((unsigned)(k >> 53) == (unsigned)B)
                atomicAdd(&hist[(unsigned)(k >> 42) & 0x7FFu], 1u);
        }
        __syncthreads();
        suffix_scan(hist, wsum);
        int extra = target - nAbove;
        {
            unsigned s0 = hist[tid];
            unsigned s0n = (tid + 1 < HBINS) ? hist[tid + 1] : 0u;
            if (s0 >= (unsigned)extra && s0n < (unsigned)extra) sc[1] = tid;
            unsigned s1 = hist[tid + NT];
            unsigned s1n = (tid + NT + 1 < HBINS) ? hist[tid + NT + 1] : 0u;
            if (s1 >= (unsigned)extra && s1n < (unsigned)extra) sc[1] = tid + NT;
        }
        if (tid == 0) sc[2] = 1;
        __syncthreads();
        refined = 1;
        B2 = sc[1];
    }
    for (int i = tid; i < n; i += NT) {
        unsigned long long k = buf[i];
        unsigned bin = (unsigned)(k >> 53);
        bool sel = (bin > (unsigned)B) ||
                   (bin == (unsigned)B &&
                    (!refined || (((unsigned)(k >> 42) & 0x7FFu) >= (unsigned)B2)));
        if (sel) {
            int p = atomicAdd(&sc[3], 1);
            if (p < LISTCAP) lst[p] = k;
        }
    }
    __syncthreads();
}

// ================= kernel A: per-batch threshold from 4096-sample =================
extern "C" __global__ void __launch_bounds__(NT)
thresh_kernel(const float* __restrict__ logits) {
    __shared__ unsigned hist[HBINS];
    __shared__ unsigned wsum[32];
    __shared__ int s_bin;
    const int tid = threadIdx.x;
    const int b = blockIdx.x;
    const float* Lp = logits + (size_t)b * NN;

    hist[tid] = 0; hist[tid + NT] = 0;
    if (tid == 0) { s_bin = 0; g_cnt[b][0] = 0; }
    __syncthreads();
    {
        float4 v = *reinterpret_cast<const float4*>(Lp + tid * 4);
        atomicAdd(&hist[flipf(__float_as_uint(v.x)) >> 21], 1u);
        atomicAdd(&hist[flipf(__float_as_uint(v.y)) >> 21], 1u);
        atomicAdd(&hist[flipf(__float_as_uint(v.z)) >> 21], 1u);
        atomicAdd(&hist[flipf(__float_as_uint(v.w)) >> 21], 1u);
    }
    __syncthreads();
    suffix_scan(hist, wsum);
    {
        unsigned s0 = hist[tid];
        unsigned s0n = (tid + 1 < HBINS) ? hist[tid + 1] : 0u;
        if (s0 >= TSAMP && s0n < TSAMP) s_bin = tid;
        unsigned s1 = hist[tid + NT];
        unsigned s1n = (tid + NT + 1 < HBINS) ? hist[tid + NT + 1] : 0u;
        if (s1 >= TSAMP && s1n < TSAMP) s_bin = tid + NT;
    }
    __syncthreads();
    if (tid == 0) {
        g_thrf[b] = (s_bin == 0) ? -CUDART_INF_F
                                 : __uint_as_float(unflipf((unsigned)s_bin << 21));
    }
}

// ================= kernel B: full-bandwidth filter stream =================
extern "C" __global__ void __launch_bounds__(256)
stream_kernel(const float* __restrict__ logits) {
    const int tid = threadIdx.x;
    const int chunk = blockIdx.x;          // 0..19
    const int b = blockIdx.y;              // 0..255
    const float* Lp = logits + (size_t)b * NN + chunk * SCH;
    const int rem = NN - chunk * SCH;
    const float thr = g_thrf[b];
    unsigned long long* gb = g_buf[b];
    int* cnt = &g_cnt[b][0];

    float4 v[4];
    bool ok[4];
    #pragma unroll
    for (int i = 0; i < 4; ++i) {          // 4 independent loads up front (MLP)
        int off = i * 1024 + tid * 4;
        ok[i] = off < rem;
        if (ok[i]) v[i] = __ldcs(reinterpret_cast<const float4*>(Lp + off));
    }
    #pragma unroll
    for (int i = 0; i < 4; ++i) {
        if (!ok[i]) continue;
        int base = chunk * SCH + i * 1024 + tid * 4;
        float4 w = v[i];
        if (w.x >= thr) append_gmem(gb, cnt, flipf(__float_as_uint(w.x)), base);
        if (w.y >= thr) append_gmem(gb, cnt, flipf(__float_as_uint(w.y)), base + 1);
        if (w.z >= thr) append_gmem(gb, cnt, flipf(__float_as_uint(w.z)), base + 2);
        if (w.w >= thr) append_gmem(gb, cnt, flipf(__float_as_uint(w.w)), base + 3);
    }
}

// ================= kernel C: select + sigmoid + exact rank + write =================
extern "C" __global__ void __launch_bounds__(NT)
select_kernel(const float* __restrict__ logits,
              const float* __restrict__ boxes,
              float* __restrict__ out) {
    extern __shared__ unsigned char smem_raw[];
    unsigned long long* buf = reinterpret_cast<unsigned long long*>(smem_raw);
    unsigned long long* lst = buf + CAP;
    unsigned* hist = reinterpret_cast<unsigned*>(lst + LISTCAP);
    __shared__ unsigned wsum[32];
    __shared__ int s_count;
    __shared__ int sc[5];

    const int tid = threadIdx.x;
    const int b = blockIdx.x;
    const float* Lp = logits + (size_t)b * NN;
    const int gcnt = g_cnt[b][0];
    int m;

    if (gcnt <= CAPG) {
        m = gcnt;
        for (int i = tid; i < m; i += NT) buf[i] = g_buf[b][i];
        __syncthreads();
    } else {
        // ---------- overflow fallback: adaptive multi-pass (never taken normally) ----------
        if (tid == 0) s_count = 0;
        __syncthreads();
        unsigned thr = 0u;
        for (int g = 0; g < 20; ++g) {
            int base = g * GSIZE + tid * 4;
            if (base < NN) {
                float4 v = *reinterpret_cast<const float4*>(Lp + base);
                unsigned ubs[4] = {flipf(__float_as_uint(v.x)), flipf(__float_as_uint(v.y)),
                                   flipf(__float_as_uint(v.z)), flipf(__float_as_uint(v.w))};
                #pragma unroll
                for (int e = 0; e < 4; ++e)
                    if (ubs[e] >= thr) append_smem(buf, &s_count, ubs[e], base + e);
            }
            __syncthreads();
            if (g == 0 || s_count > CAP - GSIZE) {
                int n = min(s_count, CAP);
                run_select(buf, lst, hist, wsum, sc, n, TSEL);
                int mm = min(sc[3], LISTCAP);
                for (int i = tid; i < mm; i += NT) buf[i] = lst[i];
                __syncthreads();
                if (tid == 0) s_count = mm;
                __syncthreads();
                thr = sc[2] ? (((unsigned)sc[0] << 21) | ((unsigned)sc[1] << 10))
                            : ((unsigned)sc[0] << 21);
            }
        }
        m = min(s_count, CAP);
    }

    // prune to ~TSEL best
    run_select(buf, lst, hist, wsum, sc, m, TSEL);
    int msel = min(sc[3], LISTCAP);

    // sigmoid rank keys: score desc, index asc
    for (int i = tid; i < msel; i += NT) {
        unsigned long long k = lst[i];
        unsigned u = (unsigned)(k >> 32);
        unsigned idx = (unsigned)k;
        float s = sigmoid_ref(__uint_as_float(unflipf(u)));
        lst[i] = ((unsigned long long)__float_as_uint(s) << 32) |
                 (unsigned)(0xFFFFFFFFu - idx);
    }
    __syncthreads();

    for (int i = tid; i < msel; i += NT) {
        unsigned long long k = lst[i];
        int r = 0;
        for (int j = 0; j < msel; ++j) r += (lst[j] > k) ? 1 : 0;
        if (r < TOPK) {
            unsigned idx = 0xFFFFFFFFu - (unsigned)k;
            float s = __uint_as_float((unsigned)(k >> 32));
            int q = (int)(idx / NC);
            int c = (int)(idx - (unsigned)q * NC);
            size_t o = (size_t)b * TOPK + (size_t)r;
            out[o] = (float)c;                                   // labels
            float4 bx = *reinterpret_cast<const float4*>(
                boxes + ((size_t)b * NQ + (size_t)q) * 4);
            float4 xy;
            xy.x = bx.x - 0.5f * bx.z;
            xy.y = bx.y - 0.5f * bx.w;
            xy.z = bx.x + 0.5f * bx.z;
            xy.w = bx.y + 0.5f * bx.w;
            *reinterpret_cast<float4*>(out + (size_t)NB * TOPK + o * 4) = xy;  // boxes
            out[(size_t)NB * TOPK * 5 + o] = s;                  // scores
        }
    }
}

extern "C" void kernel_launch(void* const* d_in, const int* in_sizes, int n_in,
                              void* d_out, int out_size) {
    const float* logits = (const float*)d_in[0];
    const float* boxes = (const float*)d_in[1];
    size_t smem = (size_t)CAP * 8 + (size_t)LISTCAP * 8 + (size_t)HBINS * 4; // 73728 B
    cudaFuncSetAttribute(select_kernel,
                         cudaFuncAttributeMaxDynamicSharedMemorySize, (int)smem);
    thresh_kernel<<<NB, NT>>>(logits);
    dim3 sg(20, NB, 1);
    stream_kernel<<<sg, 256>>>(logits);
    select_kernel<<<NB, NT, smem>>>(logits, boxes, (float*)d_out);
}